// round 7
// baseline (speedup 1.0000x reference)
#include <cuda_runtime.h>
#include <cuda_fp16.h>
#include <math.h>
#include <stdint.h>

#define NB   16
#define SEQN 20
#define PP   1024
#define VD   256
#define HND  512
#define EMBD 300
#define CIN  776
#define DHD  128

#define OFF_A0  0
#define OFF_A1  10240
#define OFF_B0  20480
#define OFF_B1  40960
#define SMEM_BYTES 61440

// ---------------- scratch ----------------
__device__ float  g_base [NB*PP*VD];
__device__ float  g_t    [NB*PP*VD];
__device__ float  g_fea1 [NB*PP*VD];
__device__ float  g_featA[NB*PP*VD];
__device__ float  g_featB[NB*PP*VD];
__device__ float  g_wsum9[9*HND*VD];
__device__ float  g_hncon[NB*9*VD];
__device__ float  g_spbase[PP*VD];
__device__ float  g_qh   [SEQN*NB*VD];
__device__ __half g_th   [NB*PP*VD];
__device__ __half g_khh  [NB*PP*VD];
__device__ __half g_vvh  [NB*PP*VD];
__device__ __half g_oh   [NB*PP*VD];
__device__ __half g_fea1h[NB*PP*VD];
__device__ __half g_lin1h[NB*PP*VD];
__device__ __half g_fAh  [NB*PP*VD];
__device__ __half g_fBh  [NB*PP*VD];
__device__ __half g_wrh  [9*VD*VD];
__device__ __half g_wkh  [VD*VD];
__device__ __half g_wvh  [VD*VD];
__device__ __half g_woh  [VD*VD];
__device__ __half g_w1h  [VD*VD];
__device__ __half g_w2h  [VD*VD];

__device__ __forceinline__ void mma16(float* d, const uint32_t* a, const uint32_t* b){
    asm volatile("mma.sync.aligned.m16n8k16.row.col.f32.f16.f16.f32 "
        "{%0,%1,%2,%3}, {%4,%5,%6,%7}, {%8,%9}, {%0,%1,%2,%3};"
        : "+f"(d[0]), "+f"(d[1]), "+f"(d[2]), "+f"(d[3])
        : "r"(a[0]), "r"(a[1]), "r"(a[2]), "r"(a[3]), "r"(b[0]), "r"(b[1]));
}

// ---------------- precompute (validated) ----------------
__global__ void k_wsum9(const float* __restrict__ w) {
    int idx = blockIdx.x*256 + threadIdx.x;
    if (idx >= 9*HND*VD) return;
    int o = idx & 255, i = (idx >> 8) & 511, t = idx >> 17;
    int ty = t/3, tx = t%3;
    int kh0 = (ty==0)?1:0, kh1 = (ty==2)?1:2;
    int kw0 = (tx==0)?1:0, kw1 = (tx==2)?1:2;
    const float* wb = w + ((size_t)o*CIN + 264 + i)*9;
    float s = 0.f;
    for (int kh=kh0; kh<=kh1; kh++)
        for (int kw=kw0; kw<=kw1; kw++)
            s += wb[kh*3+kw];
    g_wsum9[idx] = s;
}

__global__ void k_hncon(const float* __restrict__ hn) {
    int idx = blockIdx.x*256 + threadIdx.x;
    if (idx >= NB*9*VD) return;
    int o = idx & 255, t = (idx >> 8) % 9, n = idx / (9*256);
    const float* hp = hn + (size_t)n*HND;
    const float* wp = g_wsum9 + (size_t)t*HND*VD + o;
    float s = 0.f;
    for (int i=0;i<HND;i++) s += hp[i]*wp[(size_t)i*VD];
    g_hncon[idx] = s;
}

__global__ void k_spbase(const float* __restrict__ w) {
    int idx = blockIdx.x*256 + threadIdx.x;
    if (idx >= PP*VD) return;
    int o = idx & 255, p = idx >> 8;
    int hh = p >> 5, ww = p & 31;
    float s = 0.f;
    for (int kh=0;kh<3;kh++) {
        int gh = hh+kh-1; if ((unsigned)gh >= 32u) continue;
        for (int kw=0;kw<3;kw++) {
            int gw = ww+kw-1; if ((unsigned)gw >= 32u) continue;
            float xmin = gw*0.0625f - 1.f, ymin = gh*0.0625f - 1.f;
            float xmax = xmin + 0.0625f,  ymax = ymin + 0.0625f;
            const float* wb = w + ((size_t)o*CIN + 256)*9 + kh*3+kw;
            s += xmin*wb[0] + ymin*wb[9] + xmax*wb[18] + ymax*wb[27]
               + 0.5f*(xmin+xmax)*wb[36] + 0.5f*(ymin+ymax)*wb[45]
               + 0.03125f*wb[54] + 0.03125f*wb[63];
        }
    }
    g_spbase[idx] = s;
}

__global__ void k_assemble() {
    int idx = blockIdx.x*256 + threadIdx.x;
    if (idx >= NB*PP*VD/4) return;
    int e = idx*4;
    int o = e & 255, p = (e >> 8) & 1023, n = e >> 18;
    int hh = p >> 5, ww = p & 31;
    int ty = (hh==0)?0:((hh==31)?2:1);
    int tx = (ww==0)?0:((ww==31)?2:1);
    float4 sp = *(const float4*)(g_spbase + (size_t)p*VD + o);
    float4 hc = *(const float4*)(g_hncon + ((size_t)(n*9 + ty*3+tx))*VD + o);
    float4 r; r.x=sp.x+hc.x; r.y=sp.y+hc.y; r.z=sp.z+hc.z; r.w=sp.w+hc.w;
    *(float4*)(g_base + (size_t)e) = r;
}

__global__ __launch_bounds__(256) void k_qh(const float* __restrict__ emb,
                                            const float* __restrict__ qw, const float* __restrict__ qb,
                                            const float* __restrict__ Wq, const float* __restrict__ bq) {
    __shared__ float es[304];
    __shared__ float qs[256];
    int n = blockIdx.x, s = blockIdx.y, c = threadIdx.x;
    for (int i=c; i<EMBD; i+=256) es[i] = emb[((size_t)n*SEQN+s)*EMBD + i];
    __syncthreads();
    float a = qb[c];
    const float* wr = qw + (size_t)c*EMBD;
    for (int e=0;e<EMBD;e++) a += es[e]*wr[e];
    qs[c] = fmaxf(a, 0.f);
    __syncthreads();
    float a2 = bq[c];
    const float* wr2 = Wq + (size_t)c*VD;
    for (int k=0;k<VD;k++) a2 += qs[k]*wr2[k];
    g_qh[((size_t)s*NB+n)*VD + c] = a2;
}

__global__ void k_repack_h(const float* __restrict__ w){
    int idx = blockIdx.x*256 + threadIdx.x;
    if (idx >= 9*VD*VD) return;
    int i = idx & 255, o = (idx >> 8) & 255, t = idx >> 16;
    g_wrh[idx] = __float2half(w[((size_t)o*CIN + i)*9 + t]);
}

__global__ void k_half(const float* __restrict__ src, __half* __restrict__ dst, int n){
    int i = blockIdx.x*256 + threadIdx.x;
    if (2*i < n){
        float2 v = *(const float2*)(src + 2*i);
        *(__half2*)(dst + 2*i) = __floats2half2_rn(v.x, v.y);
    }
}

// ---------------- transposes ----------------
__global__ __launch_bounds__(256) void k_tr_in(const float* __restrict__ src,
                                               float* __restrict__ dst, __half* __restrict__ dsth){
    __shared__ float t[32][33];
    int n = blockIdx.z, c0 = blockIdx.y*32, p0 = blockIdx.x*32;
    int i = threadIdx.x >> 5, j = threadIdx.x & 31;
    for (int r=0;r<32;r+=8)
        t[i+r][j] = src[((size_t)n*VD + c0+i+r)*PP + p0 + j];
    __syncthreads();
    for (int r=0;r<32;r+=8){
        float v = t[j][i+r];
        size_t off = ((size_t)n*PP + p0+i+r)*VD + c0 + j;
        dst[off] = v;
        dsth[off] = __float2half(v);
    }
}
__global__ __launch_bounds__(256) void k_tr_out(const float* __restrict__ src, float* __restrict__ dst){
    __shared__ float t[32][33];
    int n = blockIdx.z, c0 = blockIdx.y*32, p0 = blockIdx.x*32;
    int i = threadIdx.x >> 5, j = threadIdx.x & 31;
    for (int r=0;r<32;r+=8)
        t[i+r][j] = src[((size_t)n*PP + p0+i+r)*VD + c0 + j];
    __syncthreads();
    for (int r=0;r<32;r+=8)
        dst[((size_t)n*VD + c0+i+r)*PP + p0 + j] = t[j][i+r];
}

// ---------------- fp16 HMMA GEMM with fused epilogues ----------------
// MODE 0: plain GEMM K=256 (grid.y=1 -> W2/bias2/C2h).  MODE 1: conv 9-tap, W=g_wrh, resid=base.
// EPI 0:+bias->Ch   1:+bias,relu->Ch   2:+bias+resid,LN->C&Ch   3:EPI2+gate   4:LN(relu(acc+resid))->C&Ch
template<int MODE, int EPI>
__global__ __launch_bounds__(512, 1) void k_tc(const __half* __restrict__ A, const __half* __restrict__ W,
    const float* __restrict__ bias, const float* __restrict__ resid,
    const float* __restrict__ lng, const float* __restrict__ lnb,
    const int* __restrict__ words, int s,
    const float* __restrict__ fcur, const __half* __restrict__ fcurh,
    float* __restrict__ C, __half* __restrict__ Ch,
    const __half* __restrict__ W2, const float* __restrict__ bias2, __half* __restrict__ C2h)
{
    extern __shared__ char smc[];
    const int tid  = threadIdx.x;
    const int lane = tid & 31;
    const int w    = tid >> 5;
    const int wm   = w & 3, wn = w >> 2;
    const int tg   = lane & 3, gp = lane >> 2;
    const int row0 = blockIdx.x*128;
    const int n    = row0 >> 10;
    const int p0   = row0 & 1023;

    if (MODE == 0 && blockIdx.y == 1){ W = W2; bias = bias2; Ch = C2h; }

    float acc[2][8][4];
#pragma unroll
    for (int f=0;f<2;f++)
#pragma unroll
        for (int nf=0;nf<8;nf++)
#pragma unroll
            for (int j=0;j<4;j++) acc[f][nf][j] = 0.f;

    const int CH = MODE ? 72 : 8;

    auto ldgA = [&](int c, uint2* r){
#pragma unroll
        for (int i=0;i<2;i++){
            int q = tid + i*512;
            int row = q>>3, c4 = q&7;
            if (MODE == 0){
                r[i] = *(const uint2*)(A + (size_t)(row0+row)*256 + c*32 + c4*4);
            } else {
                int tap = c >> 3, kb = c & 7;
                int dh = tap/3 - 1, dw = tap%3 - 1;
                int p = p0 + row;
                int sh = (p>>5) + dh, sw = (p&31) + dw;
                uint2 v = make_uint2(0u,0u);
                if ((unsigned)sh < 32u && (unsigned)sw < 32u)
                    v = *(const uint2*)(A + ((size_t)((n<<10) + (sh<<5) + sw))*256 + kb*32 + c4*4);
                r[i] = v;
            }
        }
    };
    auto ldgB = [&](int c, uint2* r){
        const __half* Wb; int k0;
        if (MODE == 0){ Wb = W; k0 = c*32; }
        else { Wb = g_wrh + (size_t)(c>>3)*VD*VD; k0 = (c&7)*32; }
#pragma unroll
        for (int i=0;i<4;i++){
            int q = tid + i*512;
            int row = q>>3, c4 = q&7;
            r[i] = *(const uint2*)(Wb + (size_t)row*256 + k0 + c4*4);
        }
    };
    auto stsA = [&](int buf, const uint2* r){
        char* As = smc + (buf ? OFF_A1 : OFF_A0);
#pragma unroll
        for (int i=0;i<2;i++){
            int q = tid + i*512;
            *(uint2*)(As + (q>>3)*80 + (q&7)*8) = r[i];
        }
    };
    auto stsB = [&](int buf, const uint2* r){
        char* Bs = smc + (buf ? OFF_B1 : OFF_B0);
#pragma unroll
        for (int i=0;i<4;i++){
            int q = tid + i*512;
            *(uint2*)(Bs + (q>>3)*80 + (q&7)*8) = r[i];
        }
    };
    auto compute = [&](int buf){
        const char* As = smc + (buf ? OFF_A1 : OFF_A0);
        const char* Bs = smc + (buf ? OFF_B1 : OFF_B0);
#pragma unroll
        for (int kk=0; kk<2; kk++){
            uint32_t af[2][4];
#pragma unroll
            for (int f=0;f<2;f++){
                int rb = wm*32 + f*16 + gp;
                af[f][0] = *(const uint32_t*)(As + rb*80     + kk*32 + tg*4);
                af[f][1] = *(const uint32_t*)(As + (rb+8)*80 + kk*32 + tg*4);
                af[f][2] = *(const uint32_t*)(As + rb*80     + kk*32 + tg*4 + 16);
                af[f][3] = *(const uint32_t*)(As + (rb+8)*80 + kk*32 + tg*4 + 16);
            }
#pragma unroll
            for (int nf=0;nf<8;nf++){
                int cb = wn*64 + nf*8 + gp;
                uint32_t bf[2];
                bf[0] = *(const uint32_t*)(Bs + cb*80 + kk*32 + tg*4);
                bf[1] = *(const uint32_t*)(Bs + cb*80 + kk*32 + tg*4 + 16);
                mma16(acc[0][nf], af[0], bf);
                mma16(acc[1][nf], af[1], bf);
            }
        }
    };

    {
        uint2 ra[2], rb[4];
        ldgA(0, ra); ldgB(0, rb);
        stsA(0, ra); stsB(0, rb);
    }
    __syncthreads();
    for (int c=0; c<CH; c++){
        uint2 ra[2], rb[4];
        if (c+1 < CH){ ldgA(c+1, ra); ldgB(c+1, rb); }
        compute(c&1);
        __syncthreads();
        if (c+1 < CH){
            stsA((c+1)&1, ra); stsB((c+1)&1, rb);
            __syncthreads();
        }
    }

    // -------- epilogue --------
    if (EPI == 3){
        if (__ldg(words + s) == 0){
#pragma unroll
            for (int f=0;f<2;f++)
#pragma unroll
            for (int nf=0;nf<8;nf++){
                int colb = wn*64 + nf*8 + 2*tg;
#pragma unroll
                for (int h=0;h<2;h++){
                    size_t off = (size_t)(row0 + wm*32 + f*16 + h*8 + gp)*256 + colb;
                    *(float2*)(C + off) = *(const float2*)(fcur + off);
                    *(uint32_t*)(Ch + off) = *(const uint32_t*)(fcurh + off);
                }
            }
            return;
        }
    }

    if (EPI <= 1){
#pragma unroll
        for (int f=0;f<2;f++)
#pragma unroll
        for (int nf=0;nf<8;nf++){
            int colb = wn*64 + nf*8 + 2*tg;
            float2 bb = *(const float2*)(bias + colb);
#pragma unroll
            for (int h=0;h<2;h++){
                int row = row0 + wm*32 + f*16 + h*8 + gp;
                float ox = acc[f][nf][2*h+0] + bb.x;
                float oy = acc[f][nf][2*h+1] + bb.y;
                if (EPI == 1){ ox = fmaxf(ox,0.f); oy = fmaxf(oy,0.f); }
                *(__half2*)(Ch + (size_t)row*256 + colb) = __floats2half2_rn(ox, oy);
            }
        }
        return;
    }

    // EPI 2/3/4: v = relu?(acc + bias? + resid), then LN
#pragma unroll
    for (int f=0;f<2;f++)
#pragma unroll
    for (int nf=0;nf<8;nf++){
        int colb = wn*64 + nf*8 + 2*tg;
        float2 bb = make_float2(0.f, 0.f);
        if (EPI != 4) bb = *(const float2*)(bias + colb);
#pragma unroll
        for (int h=0;h<2;h++){
            int row = row0 + wm*32 + f*16 + h*8 + gp;
            float2 rr = *(const float2*)(resid + (size_t)row*256 + colb);
            float vx = acc[f][nf][2*h+0] + bb.x + rr.x;
            float vy = acc[f][nf][2*h+1] + bb.y + rr.y;
            if (EPI == 4){ vx = fmaxf(vx, 0.f); vy = fmaxf(vy, 0.f); }
            acc[f][nf][2*h+0] = vx;
            acc[f][nf][2*h+1] = vy;
        }
    }
    float2* red = (float2*)smc;
#pragma unroll
    for (int f=0;f<2;f++)
#pragma unroll
    for (int h=0;h<2;h++){
        float su = 0.f, sq = 0.f;
#pragma unroll
        for (int nf=0;nf<8;nf++){
            float vx = acc[f][nf][2*h+0], vy = acc[f][nf][2*h+1];
            su += vx + vy;
            sq += vx*vx + vy*vy;
        }
        su += __shfl_xor_sync(0xffffffffu, su, 1);
        sq += __shfl_xor_sync(0xffffffffu, sq, 1);
        su += __shfl_xor_sync(0xffffffffu, su, 2);
        sq += __shfl_xor_sync(0xffffffffu, sq, 2);
        if (tg == 0){
            int rloc = wm*32 + f*16 + h*8 + gp;
            red[wn*128 + rloc] = make_float2(su, sq);
        }
    }
    __syncthreads();
#pragma unroll
    for (int f=0;f<2;f++)
#pragma unroll
    for (int h=0;h<2;h++){
        int rloc = wm*32 + f*16 + h*8 + gp;
        float S = 0.f, Q = 0.f;
#pragma unroll
        for (int w4=0;w4<4;w4++){
            float2 v = red[w4*128 + rloc];
            S += v.x; Q += v.y;
        }
        float m  = S*(1.f/256.f);
        float rs = rsqrtf(Q*(1.f/256.f) - m*m + 1e-5f);
        int row = row0 + rloc;
#pragma unroll
        for (int nf=0;nf<8;nf++){
            int colb = wn*64 + nf*8 + 2*tg;
            float2 g2 = *(const float2*)(lng + colb);
            float2 b2 = *(const float2*)(lnb + colb);
            float ox = (acc[f][nf][2*h+0]-m)*rs*g2.x + b2.x;
            float oy = (acc[f][nf][2*h+1]-m)*rs*g2.y + b2.y;
            *(float2*)(C + (size_t)row*256 + colb) = make_float2(ox, oy);
            *(__half2*)(Ch + (size_t)row*256 + colb) = __floats2half2_rn(ox, oy);
        }
    }
}

// ---------------- attention (fp16 kh/vv/o) ----------------
__global__ __launch_bounds__(256) void k_attn(int s) {
    __shared__ float ks[16*257];
    __shared__ float vs[16*257];
    __shared__ float sc[512];
    int p = blockIdx.x, tid = threadIdx.x;
    for (int idx=tid; idx<16*256; idx+=256) {
        int m = idx >> 8, c = idx & 255;
        size_t ga = ((size_t)(m*PP + p))*VD + c;
        ks[m*257+c] = __half2float(g_khh[ga]);
        vs[m*257+c] = __half2float(g_vvh[ga]);
    }
    __syncthreads();
    const float scale = 0.08838834764831845f;
#pragma unroll
    for (int rep=0; rep<2; rep++) {
        int si = tid + rep*256;
        int h = si >> 8, l = (si >> 4) & 15, m = si & 15;
        const float* qp = g_qh + ((size_t)(s*NB + l))*VD + h*DHD;
        const float* kp = ks + m*257 + h*DHD;
        float d = 0.f;
#pragma unroll 8
        for (int k=0;k<DHD;k++) d += qp[k]*kp[k];
        sc[si] = d*scale;
    }
    __syncthreads();
    if (tid < 32) {
        float* r = sc + tid*16;
        float mx = r[0];
#pragma unroll
        for (int m=1;m<16;m++) mx = fmaxf(mx, r[m]);
        float su=0.f;
#pragma unroll
        for (int m=0;m<16;m++){ float e = __expf(r[m]-mx); r[m]=e; su+=e; }
        float inv = 1.f/su;
#pragma unroll
        for (int m=0;m<16;m++) r[m]*=inv;
    }
    __syncthreads();
    for (int idx=tid; idx<4096; idx+=256) {
        int l = idx >> 8, c = idx & 255;
        int h = c >> 7;
        const float* a = sc + (h*16+l)*16;
        float accv = 0.f;
#pragma unroll
        for (int m=0;m<16;m++) accv += a[m]*vs[m*257+c];
        g_oh[((size_t)(l*PP+p))*VD + c] = __float2half(accv);
    }
}

// ---------------- launch ----------------
extern "C" void kernel_launch(void* const* d_in, const int* in_sizes, int n_in,
                              void* d_out, int out_size) {
    const float* hn         = (const float*)d_in[1];
    const float* feature    = (const float*)d_in[2];
    const float* embedding  = (const float*)d_in[3];
    const int*   words      = (const int*)  d_in[4];
    const float* qconv_w    = (const float*)d_in[5];
    const float* qconv_b    = (const float*)d_in[6];
    const float* mconv_w    = (const float*)d_in[7];
    const float* mnorm_g    = (const float*)d_in[8];
    const float* mnorm_b    = (const float*)d_in[9];
    const float* in_proj_w  = (const float*)d_in[10];
    const float* in_proj_b  = (const float*)d_in[11];
    const float* out_proj_w = (const float*)d_in[12];
    const float* out_proj_b = (const float*)d_in[13];
    const float* norm_g     = (const float*)d_in[14];
    const float* norm_b     = (const float*)d_in[15];
    const float* lin1_w     = (const float*)d_in[16];
    const float* lin1_b     = (const float*)d_in[17];
    const float* lin2_w     = (const float*)d_in[18];
    const float* lin2_b     = (const float*)d_in[19];
    const float* normf_g    = (const float*)d_in[20];
    const float* normf_b    = (const float*)d_in[21];

    cudaFuncSetAttribute(k_tc<0,0>, cudaFuncAttributeMaxDynamicSharedMemorySize, SMEM_BYTES);
    cudaFuncSetAttribute(k_tc<0,1>, cudaFuncAttributeMaxDynamicSharedMemorySize, SMEM_BYTES);
    cudaFuncSetAttribute(k_tc<0,2>, cudaFuncAttributeMaxDynamicSharedMemorySize, SMEM_BYTES);
    cudaFuncSetAttribute(k_tc<0,3>, cudaFuncAttributeMaxDynamicSharedMemorySize, SMEM_BYTES);
    cudaFuncSetAttribute(k_tc<1,4>, cudaFuncAttributeMaxDynamicSharedMemorySize, SMEM_BYTES);

    float *fA, *fB, *p_t, *p_fea1, *p_base;
    __half *fAh, *fBh, *p_th, *p_khh, *p_vvh, *p_oh, *p_fea1h, *p_lin1h;
    __half *p_wkh, *p_wvh, *p_woh, *p_w1h, *p_w2h;
    cudaGetSymbolAddress((void**)&fA,      g_featA);
    cudaGetSymbolAddress((void**)&fB,      g_featB);
    cudaGetSymbolAddress((void**)&p_t,     g_t);
    cudaGetSymbolAddress((void**)&p_fea1,  g_fea1);
    cudaGetSymbolAddress((void**)&p_base,  g_base);
    cudaGetSymbolAddress((void**)&fAh,     g_fAh);
    cudaGetSymbolAddress((void**)&fBh,     g_fBh);
    cudaGetSymbolAddress((void**)&p_th,    g_th);
    cudaGetSymbolAddress((void**)&p_khh,   g_khh);
    cudaGetSymbolAddress((void**)&p_vvh,   g_vvh);
    cudaGetSymbolAddress((void**)&p_oh,    g_oh);
    cudaGetSymbolAddress((void**)&p_fea1h, g_fea1h);
    cudaGetSymbolAddress((void**)&p_lin1h, g_lin1h);
    cudaGetSymbolAddress((void**)&p_wkh,   g_wkh);
    cudaGetSymbolAddress((void**)&p_wvh,   g_wvh);
    cudaGetSymbolAddress((void**)&p_woh,   g_woh);
    cudaGetSymbolAddress((void**)&p_w1h,   g_w1h);
    cudaGetSymbolAddress((void**)&p_w2h,   g_w2h);

    // one-time precompute
    k_wsum9    <<<(9*HND*VD+255)/256, 256>>>(mconv_w);
    k_spbase   <<<(PP*VD+255)/256,    256>>>(mconv_w);
    k_hncon    <<<(NB*9*VD+255)/256,  256>>>(hn);
    k_assemble <<<(NB*PP*VD/4+255)/256, 256>>>();
    k_qh       <<<dim3(NB,SEQN), 256>>>(embedding, qconv_w, qconv_b, in_proj_w, in_proj_b);
    k_repack_h <<<(9*VD*VD+255)/256,  256>>>(mconv_w);
    k_half     <<<128,256>>>(in_proj_w + VD*VD,   p_wkh, VD*VD);
    k_half     <<<128,256>>>(in_proj_w + 2*VD*VD, p_wvh, VD*VD);
    k_half     <<<128,256>>>(out_proj_w,          p_woh, VD*VD);
    k_half     <<<128,256>>>(lin1_w,              p_w1h, VD*VD);
    k_half     <<<128,256>>>(lin2_w,              p_w2h, VD*VD);
    k_tr_in    <<<dim3(32,8,NB), 256>>>(feature, fA, fAh);

    for (int s=0; s<SEQN; s++) {
        const float*  fin  = (s&1) ? fB  : fA;
        const __half* finh = (s&1) ? fBh : fAh;
        float*  fout  = (s&1) ? fA  : fB;
        __half* fouth = (s&1) ? fAh : fBh;

        // conv: LN(relu(conv+base)) -> g_t (fp32) + g_th (fp16)
        k_tc<1,4><<<128,512,SMEM_BYTES>>>(finh, nullptr, nullptr, p_base,
            mnorm_g, mnorm_b, nullptr, 0, nullptr, nullptr, p_t, p_th,
            nullptr, nullptr, nullptr);
        // K,V projections (merged)
        k_tc<0,0><<<dim3(128,2),512,SMEM_BYTES>>>(p_th, p_wkh, in_proj_b + VD,
            nullptr, nullptr, nullptr, nullptr, 0, nullptr, nullptr, nullptr, p_khh,
            p_wvh, in_proj_b + 2*VD, p_vvh);
        k_attn<<<PP,256>>>(s);
        // out_proj + resid(g_t) + LN -> g_fea1 + g_fea1h
        k_tc<0,2><<<128,512,SMEM_BYTES>>>(p_oh, p_woh, out_proj_b,
            p_t, norm_g, norm_b, nullptr, 0, nullptr, nullptr, p_fea1, p_fea1h,
            nullptr, nullptr, nullptr);
        // lin1 + relu -> g_lin1h
        k_tc<0,1><<<128,512,SMEM_BYTES>>>(p_fea1h, p_w1h, lin1_b,
            nullptr, nullptr, nullptr, nullptr, 0, nullptr, nullptr, nullptr, p_lin1h,
            nullptr, nullptr, nullptr);
        // lin2 + resid(g_fea1) + LN + gate -> fout + fouth
        k_tc<0,3><<<128,512,SMEM_BYTES>>>(p_lin1h, p_w2h, lin2_b,
            p_fea1, normf_g, normf_b, words, s, fin, finh, fout, fouth,
            nullptr, nullptr, nullptr);
    }
    k_tr_out<<<dim3(32,8,NB), 256>>>(fA, (float*)d_out);
}

// round 8
// speedup vs baseline: 1.0944x; 1.0944x over previous
#include <cuda_runtime.h>
#include <cuda_fp16.h>
#include <math.h>
#include <stdint.h>

#define NB   16
#define SEQN 20
#define PP   1024
#define VD   256
#define HND  512
#define EMBD 300
#define CIN  776
#define DHD  128

#define OFF_A0  0
#define OFF_A1  10240
#define OFF_B0  20480
#define OFF_B1  40960
#define SMEM_BYTES 61440

// ---------------- scratch (device globals; no allocation) ----------------
__device__ float g_base [NB*PP*VD];
__device__ float g_t    [NB*PP*VD];
__device__ float g_kh   [NB*PP*VD];
__device__ float g_vv   [NB*PP*VD];
__device__ float g_o    [NB*PP*VD];
__device__ float g_fea1 [NB*PP*VD];
__device__ float g_featA[NB*PP*VD];   // NHWC ping
__device__ float g_featB[NB*PP*VD];   // NHWC pong
__device__ float g_wsum9[9*HND*VD];
__device__ float g_hncon[NB*9*VD];
__device__ float g_spbase[PP*VD];
__device__ float g_qh   [SEQN*NB*VD];
__device__ float g_wr   [9*VD*VD];    // [tap][oc][ic]

// ---------------- helpers ----------------
__device__ __forceinline__ uint32_t h2u(__half2 h){ return *(uint32_t*)&h; }
__device__ __forceinline__ void mma16(float* d, const uint32_t* a, const uint32_t* b){
    asm volatile("mma.sync.aligned.m16n8k16.row.col.f32.f16.f16.f32 "
        "{%0,%1,%2,%3}, {%4,%5,%6,%7}, {%8,%9}, {%0,%1,%2,%3};"
        : "+f"(d[0]), "+f"(d[1]), "+f"(d[2]), "+f"(d[3])
        : "r"(a[0]), "r"(a[1]), "r"(a[2]), "r"(a[3]), "r"(b[0]), "r"(b[1]));
}
__device__ __forceinline__ void ldsm4(uint32_t* r, uint32_t addr){
    asm volatile("ldmatrix.sync.aligned.m8n8.x4.shared.b16 {%0,%1,%2,%3}, [%4];"
        : "=r"(r[0]), "=r"(r[1]), "=r"(r[2]), "=r"(r[3]) : "r"(addr));
}

// ---------------- precompute kernels (validated) ----------------
__global__ void k_wsum9(const float* __restrict__ w) {
    int idx = blockIdx.x*256 + threadIdx.x;
    if (idx >= 9*HND*VD) return;
    int o = idx & 255, i = (idx >> 8) & 511, t = idx >> 17;
    int ty = t/3, tx = t%3;
    int kh0 = (ty==0)?1:0, kh1 = (ty==2)?1:2;
    int kw0 = (tx==0)?1:0, kw1 = (tx==2)?1:2;
    const float* wb = w + ((size_t)o*CIN + 264 + i)*9;
    float s = 0.f;
    for (int kh=kh0; kh<=kh1; kh++)
        for (int kw=kw0; kw<=kw1; kw++)
            s += wb[kh*3+kw];
    g_wsum9[idx] = s;
}

__global__ void k_hncon(const float* __restrict__ hn) {
    int idx = blockIdx.x*256 + threadIdx.x;
    if (idx >= NB*9*VD) return;
    int o = idx & 255, t = (idx >> 8) % 9, n = idx / (9*256);
    const float* hp = hn + (size_t)n*HND;
    const float* wp = g_wsum9 + (size_t)t*HND*VD + o;
    float s = 0.f;
    for (int i=0;i<HND;i++) s += hp[i]*wp[(size_t)i*VD];
    g_hncon[idx] = s;
}

__global__ void k_spbase(const float* __restrict__ w) {
    int idx = blockIdx.x*256 + threadIdx.x;
    if (idx >= PP*VD) return;
    int o = idx & 255, p = idx >> 8;
    int hh = p >> 5, ww = p & 31;
    float s = 0.f;
    for (int kh=0;kh<3;kh++) {
        int gh = hh+kh-1; if ((unsigned)gh >= 32u) continue;
        for (int kw=0;kw<3;kw++) {
            int gw = ww+kw-1; if ((unsigned)gw >= 32u) continue;
            float xmin = gw*0.0625f - 1.f, ymin = gh*0.0625f - 1.f;
            float xmax = xmin + 0.0625f,  ymax = ymin + 0.0625f;
            const float* wb = w + ((size_t)o*CIN + 256)*9 + kh*3+kw;
            s += xmin*wb[0] + ymin*wb[9] + xmax*wb[18] + ymax*wb[27]
               + 0.5f*(xmin+xmax)*wb[36] + 0.5f*(ymin+ymax)*wb[45]
               + 0.03125f*wb[54] + 0.03125f*wb[63];
        }
    }
    g_spbase[idx] = s;
}

__global__ void k_assemble() {
    int idx = blockIdx.x*256 + threadIdx.x;
    if (idx >= NB*PP*VD/4) return;
    int e = idx*4;
    int o = e & 255, p = (e >> 8) & 1023, n = e >> 18;
    int hh = p >> 5, ww = p & 31;
    int ty = (hh==0)?0:((hh==31)?2:1);
    int tx = (ww==0)?0:((ww==31)?2:1);
    float4 sp = *(const float4*)(g_spbase + (size_t)p*VD + o);
    float4 hc = *(const float4*)(g_hncon + ((size_t)(n*9 + ty*3+tx))*VD + o);
    float4 r; r.x=sp.x+hc.x; r.y=sp.y+hc.y; r.z=sp.z+hc.z; r.w=sp.w+hc.w;
    *(float4*)(g_base + (size_t)e) = r;
}

__global__ __launch_bounds__(256) void k_qh(const float* __restrict__ emb,
                                            const float* __restrict__ qw, const float* __restrict__ qb,
                                            const float* __restrict__ Wq, const float* __restrict__ bq) {
    __shared__ float es[304];
    __shared__ float qs[256];
    int n = blockIdx.x, s = blockIdx.y, c = threadIdx.x;
    for (int i=c; i<EMBD; i+=256) es[i] = emb[((size_t)n*SEQN+s)*EMBD + i];
    __syncthreads();
    float a = qb[c];
    const float* wr = qw + (size_t)c*EMBD;
    for (int e=0;e<EMBD;e++) a += es[e]*wr[e];
    qs[c] = fmaxf(a, 0.f);
    __syncthreads();
    float a2 = bq[c];
    const float* wr2 = Wq + (size_t)c*VD;
    for (int k=0;k<VD;k++) a2 += qs[k]*wr2[k];
    g_qh[((size_t)s*NB+n)*VD + c] = a2;
}

__global__ void k_repack(const float* __restrict__ w){
    int idx = blockIdx.x*256 + threadIdx.x;
    if (idx >= 9*VD*VD) return;
    int i = idx & 255, o = (idx >> 8) & 255, t = idx >> 16;
    g_wr[idx] = w[((size_t)o*CIN + i)*9 + t];
}

// ---------------- transposes (once each) ----------------
__global__ __launch_bounds__(256) void k_tr_in(const float* __restrict__ src, float* __restrict__ dst){
    __shared__ float t[32][33];
    int n = blockIdx.z, c0 = blockIdx.y*32, p0 = blockIdx.x*32;
    int i = threadIdx.x >> 5, j = threadIdx.x & 31;
    for (int r=0;r<32;r+=8)
        t[i+r][j] = src[((size_t)n*VD + c0+i+r)*PP + p0 + j];
    __syncthreads();
    for (int r=0;r<32;r+=8)
        dst[((size_t)n*PP + p0+i+r)*VD + c0 + j] = t[j][i+r];
}
__global__ __launch_bounds__(256) void k_tr_out(const float* __restrict__ src, float* __restrict__ dst){
    __shared__ float t[32][33];
    int n = blockIdx.z, c0 = blockIdx.y*32, p0 = blockIdx.x*32;
    int i = threadIdx.x >> 5, j = threadIdx.x & 31;
    for (int r=0;r<32;r+=8)
        t[i+r][j] = src[((size_t)n*PP + p0+i+r)*VD + c0 + j];
    __syncthreads();
    for (int r=0;r<32;r+=8)
        dst[((size_t)n*VD + c0+i+r)*PP + p0 + j] = t[j][i+r];
}

// ---------------- fp16 HMMA GEMM: C(16384x256) = A @ W^T (+fused epilogues) -------
// MODE 0: plain GEMM, K=256 (grid.y=1 -> W2/bias2/C2).  MODE 1: conv 9-tap, W=g_wr, resid=base.
// EPI 0:+bias  1:+bias,relu  2:+bias+resid,LN  3:EPI2+word-gate(early exit)  4:LN(relu(acc+resid))
template<int MODE, int EPI>
__global__ __launch_bounds__(512, 1) void k_tc(const float* __restrict__ A, const float* __restrict__ W,
    const float* __restrict__ bias, const float* __restrict__ resid,
    const float* __restrict__ lng, const float* __restrict__ lnb,
    const int* __restrict__ words, int s, const float* __restrict__ fcur,
    float* __restrict__ C,
    const float* __restrict__ W2, const float* __restrict__ bias2, float* __restrict__ C2)
{
    extern __shared__ char smc[];
    const int tid  = threadIdx.x;
    const int lane = tid & 31;
    const int w    = tid >> 5;
    const int wm   = w & 3, wn = w >> 2;
    const int tg   = lane & 3, gp = lane >> 2;
    const int row0 = blockIdx.x*128;
    const int n    = row0 >> 10;
    const int p0   = row0 & 1023;

    if (MODE == 0 && blockIdx.y == 1){ W = W2; bias = bias2; C = C2; }

    // word-gate early exit: copy fcur -> C, skip GEMM entirely
    if (EPI == 3){
        if (__ldg(words + s) == 0){
#pragma unroll
            for (int i=0;i<16;i++){
                int q = tid + i*512;
                size_t off = (size_t)(row0 + (q>>6))*256 + (q&63)*4;
                *(float4*)(C + off) = *(const float4*)(fcur + off);
            }
            return;
        }
    }

    float acc[2][8][4];
#pragma unroll
    for (int f=0;f<2;f++)
#pragma unroll
        for (int nf=0;nf<8;nf++)
#pragma unroll
            for (int j=0;j<4;j++) acc[f][nf][j] = 0.f;

    const int CH = MODE ? 72 : 8;
    const uint32_t smb = (uint32_t)__cvta_generic_to_shared(smc);
    // ldmatrix per-lane offsets (A: tiles a0..a3; B: nf-pair tiles), 80B row stride
    const uint32_t rAoff = (uint32_t)((wm*32 + (lane&7) + ((lane>>3)&1)*8)*80 + ((lane>>4)&1)*16);
    const uint32_t rBoff = (uint32_t)((wn*64 + ((lane>>4)&1)*8 + (lane&7))*80 + ((lane>>3)&1)*16);

    auto ldgA = [&](int c, float4* r){
#pragma unroll
        for (int i=0;i<2;i++){
            int q = tid + i*512;
            int row = q>>3, c4 = q&7;
            if (MODE == 0){
                r[i] = *(const float4*)(A + (size_t)(row0+row)*256 + c*32 + c4*4);
            } else {
                int tap = c >> 3, kb = c & 7;
                int dh = tap/3 - 1, dw = tap%3 - 1;
                int p = p0 + row;
                int sh = (p>>5) + dh, sw = (p&31) + dw;
                float4 v = make_float4(0.f,0.f,0.f,0.f);
                if ((unsigned)sh < 32u && (unsigned)sw < 32u)
                    v = *(const float4*)(A + ((size_t)((n<<10) + (sh<<5) + sw))*256 + kb*32 + c4*4);
                r[i] = v;
            }
        }
    };
    auto ldgB = [&](int c, float4* r){
        const float* Wb; int k0;
        if (MODE == 0){ Wb = W; k0 = c*32; }
        else { Wb = g_wr + (size_t)(c>>3)*VD*VD; k0 = (c&7)*32; }
#pragma unroll
        for (int i=0;i<4;i++){
            int q = tid + i*512;
            r[i] = *(const float4*)(Wb + (size_t)(q>>3)*256 + k0 + (q&7)*4);
        }
    };
    auto stsA = [&](int buf, const float4* r){
        char* As = smc + (buf ? OFF_A1 : OFF_A0);
#pragma unroll
        for (int i=0;i<2;i++){
            int q = tid + i*512;
            __half2 h0 = __floats2half2_rn(r[i].x, r[i].y);
            __half2 h1 = __floats2half2_rn(r[i].z, r[i].w);
            *(uint2*)(As + (q>>3)*80 + (q&7)*8) = make_uint2(h2u(h0), h2u(h1));
        }
    };
    auto stsB = [&](int buf, const float4* r){
        char* Bs = smc + (buf ? OFF_B1 : OFF_B0);
#pragma unroll
        for (int i=0;i<4;i++){
            int q = tid + i*512;
            __half2 h0 = __floats2half2_rn(r[i].x, r[i].y);
            __half2 h1 = __floats2half2_rn(r[i].z, r[i].w);
            *(uint2*)(Bs + (q>>3)*80 + (q&7)*8) = make_uint2(h2u(h0), h2u(h1));
        }
    };
    auto compute = [&](int buf){
        uint32_t As = smb + (buf ? OFF_A1 : OFF_A0);
        uint32_t Bs = smb + (buf ? OFF_B1 : OFF_B0);
#pragma unroll
        for (int kk=0; kk<2; kk++){
            uint32_t a0[4], a1[4];
            ldsm4(a0, As + rAoff + kk*32);            // f=0: tiles a0..a3
            ldsm4(a1, As + rAoff + 16*80 + kk*32);    // f=1
#pragma unroll
            for (int nfp=0; nfp<4; nfp++){
                uint32_t b4[4];
                ldsm4(b4, Bs + rBoff + nfp*16*80 + kk*32);
                mma16(acc[0][2*nfp+0], a0, &b4[0]);
                mma16(acc[1][2*nfp+0], a1, &b4[0]);
                mma16(acc[0][2*nfp+1], a0, &b4[2]);
                mma16(acc[1][2*nfp+1], a1, &b4[2]);
            }
        }
    };

    {
        float4 ra[2], rb[4];
        ldgA(0, ra); ldgB(0, rb);
        stsA(0, ra); stsB(0, rb);
    }
    __syncthreads();
    for (int c=0; c<CH; c++){
        float4 ra[2], rb[4];
        if (c+1 < CH){ ldgA(c+1, ra); ldgB(c+1, rb); }
        compute(c&1);
        if (c+1 < CH){ stsA((c+1)&1, ra); stsB((c+1)&1, rb); }
        __syncthreads();
    }

    // -------- epilogue --------
    if (EPI <= 1){
#pragma unroll
        for (int f=0;f<2;f++)
#pragma unroll
        for (int nf=0;nf<8;nf++){
            int colb = wn*64 + nf*8 + 2*tg;
            float2 bb = *(const float2*)(bias + colb);
#pragma unroll
            for (int h=0;h<2;h++){
                int row = row0 + wm*32 + f*16 + h*8 + gp;
                float2 o;
                o.x = acc[f][nf][2*h+0] + bb.x;
                o.y = acc[f][nf][2*h+1] + bb.y;
                if (EPI == 1){ o.x = fmaxf(o.x,0.f); o.y = fmaxf(o.y,0.f); }
                *(float2*)(C + (size_t)row*256 + colb) = o;
            }
        }
        return;
    }

#pragma unroll
    for (int f=0;f<2;f++)
#pragma unroll
    for (int nf=0;nf<8;nf++){
        int colb = wn*64 + nf*8 + 2*tg;
        float2 bb = make_float2(0.f, 0.f);
        if (EPI != 4) bb = *(const float2*)(bias + colb);
#pragma unroll
        for (int h=0;h<2;h++){
            int row = row0 + wm*32 + f*16 + h*8 + gp;
            float2 rr = *(const float2*)(resid + (size_t)row*256 + colb);
            float vx = acc[f][nf][2*h+0] + bb.x + rr.x;
            float vy = acc[f][nf][2*h+1] + bb.y + rr.y;
            if (EPI == 4){ vx = fmaxf(vx, 0.f); vy = fmaxf(vy, 0.f); }
            acc[f][nf][2*h+0] = vx;
            acc[f][nf][2*h+1] = vy;
        }
    }
    float2* red = (float2*)smc;
#pragma unroll
    for (int f=0;f<2;f++)
#pragma unroll
    for (int h=0;h<2;h++){
        float su = 0.f, sq = 0.f;
#pragma unroll
        for (int nf=0;nf<8;nf++){
            float vx = acc[f][nf][2*h+0], vy = acc[f][nf][2*h+1];
            su += vx + vy;
            sq += vx*vx + vy*vy;
        }
        su += __shfl_xor_sync(0xffffffffu, su, 1);
        sq += __shfl_xor_sync(0xffffffffu, sq, 1);
        su += __shfl_xor_sync(0xffffffffu, su, 2);
        sq += __shfl_xor_sync(0xffffffffu, sq, 2);
        if (tg == 0){
            int rloc = wm*32 + f*16 + h*8 + gp;
            red[wn*128 + rloc] = make_float2(su, sq);
        }
    }
    __syncthreads();
#pragma unroll
    for (int f=0;f<2;f++)
#pragma unroll
    for (int h=0;h<2;h++){
        int rloc = wm*32 + f*16 + h*8 + gp;
        float S = 0.f, Q = 0.f;
#pragma unroll
        for (int w4=0;w4<4;w4++){
            float2 v = red[w4*128 + rloc];
            S += v.x; Q += v.y;
        }
        float m  = S*(1.f/256.f);
        float rs = rsqrtf(Q*(1.f/256.f) - m*m + 1e-5f);
        int row = row0 + rloc;
#pragma unroll
        for (int nf=0;nf<8;nf++){
            int colb = wn*64 + nf*8 + 2*tg;
            float2 g2 = *(const float2*)(lng + colb);
            float2 b2 = *(const float2*)(lnb + colb);
            float2 o;
            o.x = (acc[f][nf][2*h+0]-m)*rs*g2.x + b2.x;
            o.y = (acc[f][nf][2*h+1]-m)*rs*g2.y + b2.y;
            *(float2*)(C + (size_t)row*256 + colb) = o;
        }
    }
}

// ---------------- attention (validated) ----------------
__global__ __launch_bounds__(256) void k_attn(int s) {
    __shared__ float ks[16*257];
    __shared__ float vs[16*257];
    __shared__ float sc[512];
    int p = blockIdx.x, tid = threadIdx.x;
    for (int idx=tid; idx<16*256; idx+=256) {
        int m = idx >> 8, c = idx & 255;
        ks[m*257+c] = g_kh[((size_t)(m*PP + p))*VD + c];
        vs[m*257+c] = g_vv[((size_t)(m*PP + p))*VD + c];
    }
    __syncthreads();
    const float scale = 0.08838834764831845f;
#pragma unroll
    for (int rep=0; rep<2; rep++) {
        int si = tid + rep*256;
        int h = si >> 8, l = (si >> 4) & 15, m = si & 15;
        const float* qp = g_qh + ((size_t)(s*NB + l))*VD + h*DHD;
        const float* kp = ks + m*257 + h*DHD;
        float d = 0.f;
#pragma unroll 8
        for (int k=0;k<DHD;k++) d += qp[k]*kp[k];
        sc[si] = d*scale;
    }
    __syncthreads();
    if (tid < 32) {
        float* r = sc + tid*16;
        float mx = r[0];
#pragma unroll
        for (int m=1;m<16;m++) mx = fmaxf(mx, r[m]);
        float su=0.f;
#pragma unroll
        for (int m=0;m<16;m++){ float e = __expf(r[m]-mx); r[m]=e; su+=e; }
        float inv = 1.f/su;
#pragma unroll
        for (int m=0;m<16;m++) r[m]*=inv;
    }
    __syncthreads();
    for (int idx=tid; idx<4096; idx+=256) {
        int l = idx >> 8, c = idx & 255;
        int h = c >> 7;
        const float* a = sc + (h*16+l)*16;
        float accv = 0.f;
#pragma unroll
        for (int m=0;m<16;m++) accv += a[m]*vs[m*257+c];
        g_o[((size_t)(l*PP+p))*VD + c] = accv;
    }
}

// ---------------- launch ----------------
extern "C" void kernel_launch(void* const* d_in, const int* in_sizes, int n_in,
                              void* d_out, int out_size) {
    const float* hn         = (const float*)d_in[1];
    const float* feature    = (const float*)d_in[2];
    const float* embedding  = (const float*)d_in[3];
    const int*   words      = (const int*)  d_in[4];
    const float* qconv_w    = (const float*)d_in[5];
    const float* qconv_b    = (const float*)d_in[6];
    const float* mconv_w    = (const float*)d_in[7];
    const float* mnorm_g    = (const float*)d_in[8];
    const float* mnorm_b    = (const float*)d_in[9];
    const float* in_proj_w  = (const float*)d_in[10];
    const float* in_proj_b  = (const float*)d_in[11];
    const float* out_proj_w = (const float*)d_in[12];
    const float* out_proj_b = (const float*)d_in[13];
    const float* norm_g     = (const float*)d_in[14];
    const float* norm_b     = (const float*)d_in[15];
    const float* lin1_w     = (const float*)d_in[16];
    const float* lin1_b     = (const float*)d_in[17];
    const float* lin2_w     = (const float*)d_in[18];
    const float* lin2_b     = (const float*)d_in[19];
    const float* normf_g    = (const float*)d_in[20];
    const float* normf_b    = (const float*)d_in[21];

    cudaFuncSetAttribute(k_tc<0,0>, cudaFuncAttributeMaxDynamicSharedMemorySize, SMEM_BYTES);
    cudaFuncSetAttribute(k_tc<0,1>, cudaFuncAttributeMaxDynamicSharedMemorySize, SMEM_BYTES);
    cudaFuncSetAttribute(k_tc<0,2>, cudaFuncAttributeMaxDynamicSharedMemorySize, SMEM_BYTES);
    cudaFuncSetAttribute(k_tc<0,3>, cudaFuncAttributeMaxDynamicSharedMemorySize, SMEM_BYTES);
    cudaFuncSetAttribute(k_tc<1,4>, cudaFuncAttributeMaxDynamicSharedMemorySize, SMEM_BYTES);

    float *fA, *fB, *p_t, *p_kh, *p_vv, *p_o, *p_fea1, *p_base;
    cudaGetSymbolAddress((void**)&fA,     g_featA);
    cudaGetSymbolAddress((void**)&fB,     g_featB);
    cudaGetSymbolAddress((void**)&p_t,    g_t);
    cudaGetSymbolAddress((void**)&p_kh,   g_kh);
    cudaGetSymbolAddress((void**)&p_vv,   g_vv);
    cudaGetSymbolAddress((void**)&p_o,    g_o);
    cudaGetSymbolAddress((void**)&p_fea1, g_fea1);
    cudaGetSymbolAddress((void**)&p_base, g_base);

    // one-time precompute
    k_wsum9   <<<(9*HND*VD+255)/256, 256>>>(mconv_w);
    k_spbase  <<<(PP*VD+255)/256,    256>>>(mconv_w);
    k_hncon   <<<(NB*9*VD+255)/256,  256>>>(hn);
    k_assemble<<<(NB*PP*VD/4+255)/256, 256>>>();
    k_qh      <<<dim3(NB,SEQN), 256>>>(embedding, qconv_w, qconv_b, in_proj_w, in_proj_b);
    k_repack  <<<(9*VD*VD+255)/256,  256>>>(mconv_w);
    k_tr_in   <<<dim3(32,8,NB), 256>>>(feature, fA);

    for (int s=0; s<SEQN; s++) {
        const float* fin = (s&1) ? fB : fA;
        float* fout      = (s&1) ? fA : fB;

        // conv: LN(relu(conv + base)) -> g_t
        k_tc<1,4><<<128,512,SMEM_BYTES>>>(fin, nullptr, nullptr, p_base,
                                          mnorm_g, mnorm_b, nullptr, 0, nullptr, p_t,
                                          nullptr, nullptr, nullptr);
        // K and V projections merged: grid.y=0 -> kh, grid.y=1 -> vv
        k_tc<0,0><<<dim3(128,2),512,SMEM_BYTES>>>(p_t, in_proj_w + VD*VD, in_proj_b + VD,
                                          nullptr, nullptr, nullptr, nullptr, 0, nullptr, p_kh,
                                          in_proj_w + 2*VD*VD, in_proj_b + 2*VD, p_vv);
        k_attn <<<PP,256>>>(s);
        k_tc<0,2><<<128,512,SMEM_BYTES>>>(p_o, out_proj_w, out_proj_b,
                                          p_t, norm_g, norm_b, nullptr, 0, nullptr, p_fea1,
                                          nullptr, nullptr, nullptr);
        k_tc<0,1><<<128,512,SMEM_BYTES>>>(p_fea1, lin1_w, lin1_b,
                                          nullptr, nullptr, nullptr, nullptr, 0, nullptr, p_kh,
                                          nullptr, nullptr, nullptr);
        k_tc<0,3><<<128,512,SMEM_BYTES>>>(p_kh, lin2_w, lin2_b,
                                          p_fea1, normf_g, normf_b, words, s, fin, fout,
                                          nullptr, nullptr, nullptr);
    }
    k_tr_out<<<dim3(32,8,NB), 256>>>(fA, (float*)d_out);
}